// round 8
// baseline (speedup 1.0000x reference)
#include <cuda_runtime.h>
#include <cuda_fp16.h>

// Problem geometry
#define S      160
#define NB     4
#define SLICE  (S * S)              // 25600
#define S3     (S * S * S)          // 4,096,000
#define NVOX   (NB * S3)            // 16,384,000
#define SSIM_C1 0.0001f
#define SSIM_C2 0.0009f

// H-tiling (TH multiple of 11 -> window shifts rename away)
#define TH     22                   // outputs per block along h
#define HROWS  (TH + 10)            // 32 input rows incl. halo
#define NTILE  8                    // 8*22 = 176 >= 160 (guarded)
#define PW     172                  // padded row width

// K3 segmentation
#define DSEG   2
#define DLEN   (S / DSEG)           // 80
#define NPART  (S * NB * DSEG)      // 1280 partials

// Scratch after W+H conv, fp16 packed. Layout [n][d][h][w].
__device__ __half2 g_bufP[NVOX];    // (mu1pre, mu2pre)
__device__ __half2 g_bufQ[NVOX];    // (xx+yy, xy)
__device__ float   g_part[NPART];

// 11-tap Gaussian, sigma=1.5 (symmetric: only 6 distinct values).
#define GW_INIT { 0.00102838f, 0.00759875f, 0.03600078f, 0.10936070f, \
                  0.21300554f, 0.26601172f, 0.21300554f, 0.10936070f, \
                  0.03600078f, 0.00759875f, 0.00102838f }

// ---------------------------------------------------------------------------
// Packed f32x2 helpers (Blackwell-only; ptxas never auto-fuses these)
// ---------------------------------------------------------------------------
typedef unsigned long long ull;

__device__ __forceinline__ ull pk2(float lo, float hi) {
    ull r; asm("mov.b64 %0, {%1, %2};" : "=l"(r) : "f"(lo), "f"(hi)); return r;
}
__device__ __forceinline__ void upk2(ull v, float& lo, float& hi) {
    asm("mov.b64 {%0, %1}, %2;" : "=f"(lo), "=f"(hi) : "l"(v));
}
__device__ __forceinline__ ull fma2(ull a, ull b, ull c) {  // a*b + c
    ull d; asm("fma.rn.f32x2 %0, %1, %2, %3;" : "=l"(d) : "l"(a), "l"(b), "l"(c));
    return d;
}
__device__ __forceinline__ ull mul2(ull a, ull b) {
    ull d; asm("mul.rn.f32x2 %0, %1, %2;" : "=l"(d) : "l"(a), "l"(b));
    return d;
}

// symmetric packed coefficients: 6 distinct regs, compile-time indexed
#define G2(k) g2v[(k) < 6 ? (k) : 10 - (k)]

// ---------------------------------------------------------------------------
// K12: fused products + W-conv + H-conv, thread-per-column, f32x2 packed.
// ---------------------------------------------------------------------------
extern __shared__ float2 s_xy[];     // [HROWS][PW]

__device__ __forceinline__ void wconv_pk(
    const float2* __restrict__ r, const ull* g2v, ull& ab, ull& pq)
{
    ab = 0ull; pq = 0ull;            // (+0.f, +0.f)
    #pragma unroll
    for (int k = 0; k < 11; ++k) {
        const float2 v = r[k];
        const ull vp = pk2(v.x, v.y);
        ab = fma2(G2(k), vp, ab);                 // A += g a ; B += g b
        const ull m = mul2(vp, vp);               // (a^2, b^2)
        float mx, my; upk2(m, mx, my);
        const ull t = pk2(mx + my, v.x * v.y);    // (a^2+b^2, ab)
        pq = fma2(G2(k), t, pq);                  // P += g(..) ; Q += g(ab)
    }
}

__global__ __launch_bounds__(160, 4) void k12_wh(
    const float* __restrict__ x, const float* __restrict__ y)
{
    const float GW[11] = GW_INIT;
    ull g2v[6];
    #pragma unroll
    for (int k = 0; k < 6; ++k) g2v[k] = pk2(GW[k], GW[k]);

    const int ht = blockIdx.x;
    const int d  = blockIdx.y;
    const int n  = blockIdx.z;
    const int h0 = ht * TH;
    const int tid = threadIdx.x;
    const size_t sbase = (size_t)n * S3 + (size_t)d * SLICE;

    // Load HROWS padded input rows (zeros at h and w edges), coalesced.
    for (int i = tid; i < HROWS * PW; i += 160) {
        const int r = i / PW, p = i - r * PW;
        const int hh = h0 - 5 + r;
        const int ww = p - 6;          // col p holds w = p-6
        float a = 0.f, b = 0.f;
        if (hh >= 0 && hh < S && ww >= 0 && ww < S) {
            const size_t g = sbase + (size_t)hh * S + ww;
            a = x[g]; b = y[g];
        }
        s_xy[i] = make_float2(a, b);
    }
    __syncthreads();

    const int w = tid;
    const int cbase = w + 1;           // padded col of tap k: w+1+k

    ull wab[11], wpq[11];
    #pragma unroll
    for (int k = 0; k < 11; ++k)
        wconv_pk(s_xy + k * PW + cbase, g2v, wab[k], wpq[k]);

    for (int ob = 0; ob < TH; ob += 11) {
        #pragma unroll
        for (int u = 0; u < 11; ++u) {
            const int o = ob + u;
            const int h = h0 + o;
            if (h < S) {
                ull accAB = 0ull, accPQ = 0ull;
                #pragma unroll
                for (int k = 0; k < 11; ++k) {
                    accAB = fma2(G2(k), wab[k], accAB);
                    accPQ = fma2(G2(k), wpq[k], accPQ);
                }
                float A, B, P, Q;
                upk2(accAB, A, B);
                upk2(accPQ, P, Q);
                const size_t o_idx = sbase + (size_t)h * S + w;
                g_bufP[o_idx] = __floats2half2_rn(A, B);
                g_bufQ[o_idx] = __floats2half2_rn(P, Q);
            }
            #pragma unroll
            for (int k = 0; k < 10; ++k) {
                wab[k] = wab[k+1]; wpq[k] = wpq[k+1];
            }
            if (o + 11 < HROWS)
                wconv_pk(s_xy + (o + 11) * PW + cbase, g2v, wab[10], wpq[10]);
        }
    }
}

// ---------------------------------------------------------------------------
// K3: conv along D (2 segments of 80), f32x2 packed, + SSIM + partials.
// ---------------------------------------------------------------------------
__global__ __launch_bounds__(S) void k3_dconv_ssim()
{
    const float GW[11] = GW_INIT;
    ull g2v[6];
    #pragma unroll
    for (int k = 0; k < 6; ++k) g2v[k] = pk2(GW[k], GW[k]);

    const int h   = blockIdx.x;
    const int n   = blockIdx.y;
    const int seg = blockIdx.z;
    const int d0  = seg * DLEN;
    const int w   = threadIdx.x;

    const size_t off = (size_t)n * S3 + (size_t)h * S + w;
    const __half2* __restrict__ pP = g_bufP + off;
    const __half2* __restrict__ pQ = g_bufQ + off;

    ull wab[11], wpq[11];
    #pragma unroll
    for (int k = 0; k < 11; ++k) {
        const int dd = d0 - 5 + k;
        if (dd >= 0 && dd < S) {
            const size_t ds = (size_t)dd * SLICE;
            const float2 vp = __half22float2(pP[ds]);
            const float2 vq = __half22float2(pQ[ds]);
            wab[k] = pk2(vp.x, vp.y);
            wpq[k] = pk2(vq.x, vq.y);
        } else {
            wab[k] = 0ull; wpq[k] = 0ull;
        }
    }

    float lsum = 0.f;

    for (int ob = 0; ob < 88; ob += 11) {
        #pragma unroll
        for (int u = 0; u < 11; ++u) {
            const int o = ob + u;          // local output index
            if (o < DLEN) {
                ull accAB = 0ull, accPQ = 0ull;
                #pragma unroll
                for (int k = 0; k < 11; ++k) {
                    accAB = fma2(G2(k), wab[k], accAB);
                    accPQ = fma2(G2(k), wpq[k], accPQ);
                }
                float mu1, mu2, pp, qq;
                upk2(accAB, mu1, mu2);
                upk2(accPQ, pp, qq);
                const float mu1sq = mu1 * mu1;
                const float mu2sq = mu2 * mu2;
                const float mu12  = mu1 * mu2;
                const float s1s2  = pp - mu1sq - mu2sq;
                const float s12   = qq - mu12;
                const float num = (2.f * mu12 + SSIM_C1) * (2.f * s12 + SSIM_C2);
                const float den = (mu1sq + mu2sq + SSIM_C1) * (s1s2 + SSIM_C2);
                lsum += __fdividef(num, den);
            }
            #pragma unroll
            for (int k = 0; k < 10; ++k) {
                wab[k] = wab[k+1]; wpq[k] = wpq[k+1];
            }
            const int dd = d0 + o + 6;
            if (o < DLEN - 1 && dd < S) {
                const size_t ds = (size_t)dd * SLICE;
                const float2 vp = __half22float2(pP[ds]);
                const float2 vq = __half22float2(pQ[ds]);
                wab[10] = pk2(vp.x, vp.y);
                wpq[10] = pk2(vq.x, vq.y);
            } else {
                wab[10] = 0ull; wpq[10] = 0ull;
            }
        }
    }

    #pragma unroll
    for (int t = 16; t > 0; t >>= 1)
        lsum += __shfl_xor_sync(0xffffffffu, lsum, t);
    __shared__ float red[5];
    const int wid = w >> 5, lane = w & 31;
    if (lane == 0) red[wid] = lsum;
    __syncthreads();
    if (w == 0) {
        const int b = blockIdx.x + S * (blockIdx.y + NB * blockIdx.z);
        g_part[b] = red[0] + red[1] + red[2] + red[3] + red[4];
    }
}

// ---------------------------------------------------------------------------
// K4: reduce 1280 partials -> scalar loss
// ---------------------------------------------------------------------------
__global__ __launch_bounds__(256) void k4_finalize(float* __restrict__ out)
{
    const int tid = threadIdx.x;
    float s = 0.f;
    for (int i = tid; i < NPART; i += 256) s += g_part[i];
    #pragma unroll
    for (int t = 16; t > 0; t >>= 1)
        s += __shfl_xor_sync(0xffffffffu, s, t);
    __shared__ float red[8];
    if ((tid & 31) == 0) red[tid >> 5] = s;
    __syncthreads();
    if (tid == 0) {
        float tot = 0.f;
        #pragma unroll
        for (int i = 0; i < 8; ++i) tot += red[i];
        out[0] = (float)(1.0 - (double)tot / (double)NVOX);
    }
}

// ---------------------------------------------------------------------------
extern "C" void kernel_launch(void* const* d_in, const int* in_sizes, int n_in,
                              void* d_out, int out_size)
{
    const float* img1 = (const float*)d_in[0];
    const float* img2 = (const float*)d_in[1];
    float* out = (float*)d_out;

    const int k12_smem = HROWS * PW * (int)sizeof(float2);   // 44032 B
    cudaFuncSetAttribute(k12_wh, cudaFuncAttributeMaxDynamicSharedMemorySize,
                         k12_smem);

    k12_wh<<<dim3(NTILE, S, NB), 160, k12_smem>>>(img1, img2);
    k3_dconv_ssim<<<dim3(S, NB, DSEG), S>>>();
    k4_finalize<<<1, 256>>>(out);
}

// round 9
// speedup vs baseline: 1.0176x; 1.0176x over previous
#include <cuda_runtime.h>
#include <cuda_fp16.h>

// Problem geometry
#define S      160
#define NB     4
#define SLICE  (S * S)              // 25600
#define S3     (S * S * S)          // 4,096,000
#define NVOX   (NB * S3)            // 16,384,000
#define SSIM_C1 0.0001f
#define SSIM_C2 0.0009f

// H-tiling (TH multiple of 11 -> window shifts rename away)
#define TH     22                   // outputs per block along h
#define HROWS  (TH + 10)            // 32 input rows incl. halo
#define NTILE  8                    // 8*22 = 176 >= 160 (guarded)
#define PW     172                  // padded row width

// K3 segmentation
#define DSEG   2
#define DLEN   (S / DSEG)           // 80
#define NPART  (S * NB * DSEG)      // 1280 partials

// Scratch after W+H conv. One uint2 per voxel:
//   .x = half2(mu1pre, mu2pre), .y = half2(xx+yy, xy). Layout [n][d][h][w].
__device__ uint2 g_buf[NVOX];
__device__ float g_part[NPART];

// 11-tap Gaussian, sigma=1.5 (symmetric: 6 distinct values).
#define GW_INIT { 0.00102838f, 0.00759875f, 0.03600078f, 0.10936070f, \
                  0.21300554f, 0.26601172f, 0.21300554f, 0.10936070f, \
                  0.03600078f, 0.00759875f, 0.00102838f }

// ---------------------------------------------------------------------------
// Packed f32x2 helpers (Blackwell; ptxas never auto-fuses these)
// ---------------------------------------------------------------------------
typedef unsigned long long ull;

__device__ __forceinline__ ull pk2(float lo, float hi) {
    ull r; asm("mov.b64 %0, {%1, %2};" : "=l"(r) : "f"(lo), "f"(hi)); return r;
}
__device__ __forceinline__ void upk2(ull v, float& lo, float& hi) {
    asm("mov.b64 {%0, %1}, %2;" : "=f"(lo), "=f"(hi) : "l"(v));
}
__device__ __forceinline__ ull fma2(ull a, ull b, ull c) {
    ull d; asm("fma.rn.f32x2 %0, %1, %2, %3;" : "=l"(d) : "l"(a), "l"(b), "l"(c));
    return d;
}
__device__ __forceinline__ ull mul2(ull a, ull b) {
    ull d; asm("mul.rn.f32x2 %0, %1, %2;" : "=l"(d) : "l"(a), "l"(b));
    return d;
}

#define G2(k) g2v[(k) < 6 ? (k) : 10 - (k)]

__device__ __forceinline__ unsigned h2u(__half2 h) {
    return *reinterpret_cast<unsigned*>(&h);
}
__device__ __forceinline__ __half2 u2h(unsigned u) {
    return *reinterpret_cast<__half2*>(&u);
}

// ---------------------------------------------------------------------------
// K12: fused products + W-conv + H-conv, thread-per-column.
// Window channels: packed (a,b)-conv, packed (a^2,b^2)-conv, scalar ab-conv.
// 5 math ops per tap, no pack/unpack in the tap loop.
// ---------------------------------------------------------------------------
extern __shared__ float2 s_xy[];     // [HROWS][PW]

__device__ __forceinline__ void wconv3(
    const float2* __restrict__ r, const ull* g2v, const float* GW,
    ull& ab, ull& sq, float& q)
{
    ab = 0ull; sq = 0ull; q = 0.f;
    #pragma unroll
    for (int k = 0; k < 11; ++k) {
        const float2 v = r[k];
        const ull vp = pk2(v.x, v.y);          // register-pair rename
        ab = fma2(G2(k), vp, ab);              // (Sg*a, Sg*b)
        const ull m = mul2(vp, vp);            // (a^2, b^2)
        sq = fma2(G2(k), m, sq);               // (Sg*a^2, Sg*b^2)
        q  = fmaf(GW[k], v.x * v.y, q);        // Sg*ab
    }
}

__global__ __launch_bounds__(160, 4) void k12_wh(
    const float* __restrict__ x, const float* __restrict__ y)
{
    const float GW[11] = GW_INIT;
    ull g2v[6];
    #pragma unroll
    for (int k = 0; k < 6; ++k) g2v[k] = pk2(GW[k], GW[k]);

    const int ht = blockIdx.x;
    const int d  = blockIdx.y;
    const int n  = blockIdx.z;
    const int h0 = ht * TH;
    const int tid = threadIdx.x;
    const size_t sbase = (size_t)n * S3 + (size_t)d * SLICE;

    // Load HROWS padded input rows (zeros at h and w edges), coalesced.
    for (int i = tid; i < HROWS * PW; i += 160) {
        const int r = i / PW, p = i - r * PW;
        const int hh = h0 - 5 + r;
        const int ww = p - 6;          // col p holds w = p-6
        float a = 0.f, b = 0.f;
        if (hh >= 0 && hh < S && ww >= 0 && ww < S) {
            const size_t g = sbase + (size_t)hh * S + ww;
            a = x[g]; b = y[g];
        }
        s_xy[i] = make_float2(a, b);
    }
    __syncthreads();

    const int w = tid;
    const int cbase = w + 1;           // padded col of tap k: w+1+k

    ull wab[11], wsq[11];
    float wq[11];
    #pragma unroll
    for (int k = 0; k < 11; ++k)
        wconv3(s_xy + k * PW + cbase, g2v, GW, wab[k], wsq[k], wq[k]);

    for (int ob = 0; ob < TH; ob += 11) {
        #pragma unroll
        for (int u = 0; u < 11; ++u) {
            const int o = ob + u;
            const int h = h0 + o;
            if (h < S) {
                ull accAB = 0ull, accSQ = 0ull;
                float accQ = 0.f;
                #pragma unroll
                for (int k = 0; k < 11; ++k) {
                    accAB = fma2(G2(k), wab[k], accAB);
                    accSQ = fma2(G2(k), wsq[k], accSQ);
                    accQ  = fmaf(GW[k], wq[k], accQ);
                }
                float A, B, sx, sy;
                upk2(accAB, A, B);
                upk2(accSQ, sx, sy);
                uint2 st;
                st.x = h2u(__floats2half2_rn(A, B));
                st.y = h2u(__floats2half2_rn(sx + sy, accQ));
                g_buf[sbase + (size_t)h * S + w] = st;
            }
            #pragma unroll
            for (int k = 0; k < 10; ++k) {
                wab[k] = wab[k+1]; wsq[k] = wsq[k+1]; wq[k] = wq[k+1];
            }
            if (o + 11 < HROWS)
                wconv3(s_xy + (o + 11) * PW + cbase, g2v, GW,
                       wab[10], wsq[10], wq[10]);
        }
    }
}

// ---------------------------------------------------------------------------
// K3: conv along D (2 segments of 80) + fused SSIM + block partials.
// Scalar math (R7 form); one LDG.64 per d-step.
// ---------------------------------------------------------------------------
__global__ __launch_bounds__(S) void k3_dconv_ssim()
{
    const float GW[11] = GW_INIT;
    const int h   = blockIdx.x;
    const int n   = blockIdx.y;
    const int seg = blockIdx.z;
    const int d0  = seg * DLEN;
    const int w   = threadIdx.x;

    const uint2* __restrict__ src =
        g_buf + (size_t)n * S3 + (size_t)h * S + w;

    float w0[11], w1[11], w2[11], w3[11];
    #pragma unroll
    for (int k = 0; k < 11; ++k) {
        const int dd = d0 - 5 + k;
        if (dd >= 0 && dd < S) {
            const uint2 v = src[(size_t)dd * SLICE];
            const float2 vp = __half22float2(u2h(v.x));
            const float2 vq = __half22float2(u2h(v.y));
            w0[k] = vp.x; w1[k] = vp.y; w2[k] = vq.x; w3[k] = vq.y;
        } else {
            w0[k] = 0.f; w1[k] = 0.f; w2[k] = 0.f; w3[k] = 0.f;
        }
    }

    float lsum = 0.f;

    for (int ob = 0; ob < 88; ob += 11) {
        #pragma unroll
        for (int u = 0; u < 11; ++u) {
            const int o = ob + u;
            if (o < DLEN) {
                float mu1 = 0.f, mu2 = 0.f, pp = 0.f, qq = 0.f;
                #pragma unroll
                for (int k = 0; k < 11; ++k) {
                    const float g = GW[k];
                    mu1 += g * w0[k]; mu2 += g * w1[k];
                    pp  += g * w2[k]; qq  += g * w3[k];
                }
                const float mu1sq = mu1 * mu1;
                const float mu2sq = mu2 * mu2;
                const float mu12  = mu1 * mu2;
                const float s1s2  = pp - mu1sq - mu2sq;
                const float s12   = qq - mu12;
                const float num = (2.f * mu12 + SSIM_C1) * (2.f * s12 + SSIM_C2);
                const float den = (mu1sq + mu2sq + SSIM_C1) * (s1s2 + SSIM_C2);
                lsum += __fdividef(num, den);
            }
            #pragma unroll
            for (int k = 0; k < 10; ++k) {
                w0[k] = w0[k+1]; w1[k] = w1[k+1];
                w2[k] = w2[k+1]; w3[k] = w3[k+1];
            }
            const int dd = d0 + o + 6;
            if (o < DLEN - 1 && dd < S) {
                const uint2 v = src[(size_t)dd * SLICE];
                const float2 vp = __half22float2(u2h(v.x));
                const float2 vq = __half22float2(u2h(v.y));
                w0[10] = vp.x; w1[10] = vp.y; w2[10] = vq.x; w3[10] = vq.y;
            } else {
                w0[10] = 0.f; w1[10] = 0.f; w2[10] = 0.f; w3[10] = 0.f;
            }
        }
    }

    #pragma unroll
    for (int t = 16; t > 0; t >>= 1)
        lsum += __shfl_xor_sync(0xffffffffu, lsum, t);
    __shared__ float red[5];
    const int wid = w >> 5, lane = w & 31;
    if (lane == 0) red[wid] = lsum;
    __syncthreads();
    if (w == 0) {
        const int b = blockIdx.x + S * (blockIdx.y + NB * blockIdx.z);
        g_part[b] = red[0] + red[1] + red[2] + red[3] + red[4];
    }
}

// ---------------------------------------------------------------------------
// K4: reduce 1280 partials -> scalar loss
// ---------------------------------------------------------------------------
__global__ __launch_bounds__(256) void k4_finalize(float* __restrict__ out)
{
    const int tid = threadIdx.x;
    float s = 0.f;
    for (int i = tid; i < NPART; i += 256) s += g_part[i];
    #pragma unroll
    for (int t = 16; t > 0; t >>= 1)
        s += __shfl_xor_sync(0xffffffffu, s, t);
    __shared__ float red[8];
    if ((tid & 31) == 0) red[tid >> 5] = s;
    __syncthreads();
    if (tid == 0) {
        float tot = 0.f;
        #pragma unroll
        for (int i = 0; i < 8; ++i) tot += red[i];
        out[0] = (float)(1.0 - (double)tot / (double)NVOX);
    }
}

// ---------------------------------------------------------------------------
extern "C" void kernel_launch(void* const* d_in, const int* in_sizes, int n_in,
                              void* d_out, int out_size)
{
    const float* img1 = (const float*)d_in[0];
    const float* img2 = (const float*)d_in[1];
    float* out = (float*)d_out;

    const int k12_smem = HROWS * PW * (int)sizeof(float2);   // 44032 B
    cudaFuncSetAttribute(k12_wh, cudaFuncAttributeMaxDynamicSharedMemorySize,
                         k12_smem);

    k12_wh<<<dim3(NTILE, S, NB), 160, k12_smem>>>(img1, img2);
    k3_dconv_ssim<<<dim3(S, NB, DSEG), S>>>();
    k4_finalize<<<1, 256>>>(out);
}

// round 10
// speedup vs baseline: 1.2533x; 1.2316x over previous
#include <cuda_runtime.h>
#include <cuda_fp16.h>

// Problem geometry
#define S      160
#define NB     4
#define SLICE  (S * S)              // 25600
#define S3     (S * S * S)          // 4,096,000
#define NVOX   (NB * S3)            // 16,384,000
#define SSIM_C1 0.0001f
#define SSIM_C2 0.0009f

// H-tiling (TH multiple of 11 -> window shifts rename away)
#define TH     22                   // outputs per block along h
#define HROWS  (TH + 10)            // 32 input rows incl. halo
#define NTILE  8                    // 8*22 = 176 >= 160 (guarded)
#define PW     172                  // padded row width

// K3 segmentation
#define DSEG   2
#define DLEN   (S / DSEG)           // 80
#define NPART  (S * NB * DSEG)      // 1280 partials

// Scratch after W+H conv. One uint2 per voxel:
//   .x = half2(mu1pre, mu2pre), .y = half2(xx+yy, xy).
// Layout [n][h][d][w]  ->  K3's D-conv steps are 1280B-stride (L2-local).
__device__ uint2 g_buf[NVOX];
__device__ float g_part[NPART];

// 11-tap Gaussian, sigma=1.5 (symmetric: 6 distinct values).
#define GW_INIT { 0.00102838f, 0.00759875f, 0.03600078f, 0.10936070f, \
                  0.21300554f, 0.26601172f, 0.21300554f, 0.10936070f, \
                  0.03600078f, 0.00759875f, 0.00102838f }

// ---------------------------------------------------------------------------
// Packed f32x2 helpers (Blackwell; ptxas never auto-fuses these)
// ---------------------------------------------------------------------------
typedef unsigned long long ull;

__device__ __forceinline__ ull pk2(float lo, float hi) {
    ull r; asm("mov.b64 %0, {%1, %2};" : "=l"(r) : "f"(lo), "f"(hi)); return r;
}
__device__ __forceinline__ void upk2(ull v, float& lo, float& hi) {
    asm("mov.b64 {%0, %1}, %2;" : "=f"(lo), "=f"(hi) : "l"(v));
}
__device__ __forceinline__ ull fma2(ull a, ull b, ull c) {
    ull d; asm("fma.rn.f32x2 %0, %1, %2, %3;" : "=l"(d) : "l"(a), "l"(b), "l"(c));
    return d;
}
__device__ __forceinline__ ull mul2(ull a, ull b) {
    ull d; asm("mul.rn.f32x2 %0, %1, %2;" : "=l"(d) : "l"(a), "l"(b));
    return d;
}

#define G2(k) g2v[(k) < 6 ? (k) : 10 - (k)]

__device__ __forceinline__ unsigned h2u(__half2 h) {
    return *reinterpret_cast<unsigned*>(&h);
}
__device__ __forceinline__ __half2 u2h(unsigned u) {
    return *reinterpret_cast<__half2*>(&u);
}

// ---------------------------------------------------------------------------
// K12: fused products + W-conv + H-conv, thread-per-column (R8 wconv form).
// Window channels: packed (a,b)-conv and packed (a^2+b^2, ab)-conv.
// ---------------------------------------------------------------------------
extern __shared__ float2 s_xy[];     // [HROWS][PW]

__device__ __forceinline__ void wconv_pk(
    const float2* __restrict__ r, const ull* g2v, ull& ab, ull& pq)
{
    ab = 0ull; pq = 0ull;
    #pragma unroll
    for (int k = 0; k < 11; ++k) {
        const float2 v = r[k];
        const ull vp = pk2(v.x, v.y);
        ab = fma2(G2(k), vp, ab);                 // (Sg*a, Sg*b)
        const ull m = mul2(vp, vp);               // (a^2, b^2)
        float mx, my; upk2(m, mx, my);
        const ull t = pk2(mx + my, v.x * v.y);    // (a^2+b^2, ab)
        pq = fma2(G2(k), t, pq);
    }
}

__global__ __launch_bounds__(160, 5) void k12_wh(
    const float* __restrict__ x, const float* __restrict__ y)
{
    const float GW[11] = GW_INIT;
    ull g2v[6];
    #pragma unroll
    for (int k = 0; k < 6; ++k) g2v[k] = pk2(GW[k], GW[k]);

    const int ht = blockIdx.x;
    const int d  = blockIdx.y;
    const int n  = blockIdx.z;
    const int h0 = ht * TH;
    const int tid = threadIdx.x;
    const size_t ibase = (size_t)n * S3 + (size_t)d * SLICE;   // input slice

    // Load HROWS padded input rows (zeros at h and w edges), coalesced.
    for (int i = tid; i < HROWS * PW; i += 160) {
        const int r = i / PW, p = i - r * PW;
        const int hh = h0 - 5 + r;
        const int ww = p - 6;          // col p holds w = p-6
        float a = 0.f, b = 0.f;
        if (hh >= 0 && hh < S && ww >= 0 && ww < S) {
            const size_t g = ibase + (size_t)hh * S + ww;
            a = x[g]; b = y[g];
        }
        s_xy[i] = make_float2(a, b);
    }
    __syncthreads();

    const int w = tid;
    const int cbase = w + 1;           // padded col of tap k: w+1+k

    ull wab[11], wpq[11];
    #pragma unroll
    for (int k = 0; k < 11; ++k)
        wconv_pk(s_xy + k * PW + cbase, g2v, wab[k], wpq[k]);

    // output base for layout [n][h][d][w]
    const size_t obase = (size_t)n * S3 + (size_t)d * S + w;

    for (int ob = 0; ob < TH; ob += 11) {
        #pragma unroll
        for (int u = 0; u < 11; ++u) {
            const int o = ob + u;
            const int h = h0 + o;
            if (h < S) {
                ull accAB = 0ull, accPQ = 0ull;
                #pragma unroll
                for (int k = 0; k < 11; ++k) {
                    accAB = fma2(G2(k), wab[k], accAB);
                    accPQ = fma2(G2(k), wpq[k], accPQ);
                }
                float A, B, P, Q;
                upk2(accAB, A, B);
                upk2(accPQ, P, Q);
                uint2 st;
                st.x = h2u(__floats2half2_rn(A, B));
                st.y = h2u(__floats2half2_rn(P, Q));
                g_buf[obase + (size_t)h * SLICE] = st;
            }
            #pragma unroll
            for (int k = 0; k < 10; ++k) {
                wab[k] = wab[k+1]; wpq[k] = wpq[k+1];
            }
            if (o + 11 < HROWS)
                wconv_pk(s_xy + (o + 11) * PW + cbase, g2v, wab[10], wpq[10]);
        }
    }
}

// ---------------------------------------------------------------------------
// K3: conv along D (2 segments of 80) + fused SSIM + block partials.
// Layout [n][h][d][w]: d-steps are 1280B apart -> sequential 200KB stream.
// ---------------------------------------------------------------------------
__global__ __launch_bounds__(S) void k3_dconv_ssim()
{
    const float GW[11] = GW_INIT;
    const int h   = blockIdx.x;
    const int n   = blockIdx.y;
    const int seg = blockIdx.z;
    const int d0  = seg * DLEN;
    const int w   = threadIdx.x;

    const uint2* __restrict__ src =
        g_buf + (size_t)n * S3 + (size_t)h * SLICE + w;

    float w0[11], w1[11], w2[11], w3[11];
    #pragma unroll
    for (int k = 0; k < 11; ++k) {
        const int dd = d0 - 5 + k;
        if (dd >= 0 && dd < S) {
            const uint2 v = src[(size_t)dd * S];
            const float2 vp = __half22float2(u2h(v.x));
            const float2 vq = __half22float2(u2h(v.y));
            w0[k] = vp.x; w1[k] = vp.y; w2[k] = vq.x; w3[k] = vq.y;
        } else {
            w0[k] = 0.f; w1[k] = 0.f; w2[k] = 0.f; w3[k] = 0.f;
        }
    }

    float lsum = 0.f;

    for (int ob = 0; ob < 88; ob += 11) {
        #pragma unroll
        for (int u = 0; u < 11; ++u) {
            const int o = ob + u;
            if (o < DLEN) {
                float mu1 = 0.f, mu2 = 0.f, pp = 0.f, qq = 0.f;
                #pragma unroll
                for (int k = 0; k < 11; ++k) {
                    const float g = GW[k];
                    mu1 += g * w0[k]; mu2 += g * w1[k];
                    pp  += g * w2[k]; qq  += g * w3[k];
                }
                const float mu1sq = mu1 * mu1;
                const float mu2sq = mu2 * mu2;
                const float mu12  = mu1 * mu2;
                const float s1s2  = pp - mu1sq - mu2sq;
                const float s12   = qq - mu12;
                const float num = (2.f * mu12 + SSIM_C1) * (2.f * s12 + SSIM_C2);
                const float den = (mu1sq + mu2sq + SSIM_C1) * (s1s2 + SSIM_C2);
                lsum += __fdividef(num, den);
            }
            #pragma unroll
            for (int k = 0; k < 10; ++k) {
                w0[k] = w0[k+1]; w1[k] = w1[k+1];
                w2[k] = w2[k+1]; w3[k] = w3[k+1];
            }
            const int dd = d0 + o + 6;
            if (o < DLEN - 1 && dd < S) {
                const uint2 v = src[(size_t)dd * S];
                const float2 vp = __half22float2(u2h(v.x));
                const float2 vq = __half22float2(u2h(v.y));
                w0[10] = vp.x; w1[10] = vp.y; w2[10] = vq.x; w3[10] = vq.y;
            } else {
                w0[10] = 0.f; w1[10] = 0.f; w2[10] = 0.f; w3[10] = 0.f;
            }
        }
    }

    #pragma unroll
    for (int t = 16; t > 0; t >>= 1)
        lsum += __shfl_xor_sync(0xffffffffu, lsum, t);
    __shared__ float red[5];
    const int wid = w >> 5, lane = w & 31;
    if (lane == 0) red[wid] = lsum;
    __syncthreads();
    if (w == 0) {
        const int b = blockIdx.x + S * (blockIdx.y + NB * blockIdx.z);
        g_part[b] = red[0] + red[1] + red[2] + red[3] + red[4];
    }
}

// ---------------------------------------------------------------------------
// K4: reduce 1280 partials -> scalar loss
// ---------------------------------------------------------------------------
__global__ __launch_bounds__(256) void k4_finalize(float* __restrict__ out)
{
    const int tid = threadIdx.x;
    float s = 0.f;
    for (int i = tid; i < NPART; i += 256) s += g_part[i];
    #pragma unroll
    for (int t = 16; t > 0; t >>= 1)
        s += __shfl_xor_sync(0xffffffffu, s, t);
    __shared__ float red[8];
    if ((tid & 31) == 0) red[tid >> 5] = s;
    __syncthreads();
    if (tid == 0) {
        float tot = 0.f;
        #pragma unroll
        for (int i = 0; i < 8; ++i) tot += red[i];
        out[0] = (float)(1.0 - (double)tot / (double)NVOX);
    }
}

// ---------------------------------------------------------------------------
extern "C" void kernel_launch(void* const* d_in, const int* in_sizes, int n_in,
                              void* d_out, int out_size)
{
    const float* img1 = (const float*)d_in[0];
    const float* img2 = (const float*)d_in[1];
    float* out = (float*)d_out;

    const int k12_smem = HROWS * PW * (int)sizeof(float2);   // 44032 B
    cudaFuncSetAttribute(k12_wh, cudaFuncAttributeMaxDynamicSharedMemorySize,
                         k12_smem);

    k12_wh<<<dim3(NTILE, S, NB), 160, k12_smem>>>(img1, img2);
    k3_dconv_ssim<<<dim3(S, NB, DSEG), S>>>();
    k4_finalize<<<1, 256>>>(out);
}

// round 11
// speedup vs baseline: 1.3541x; 1.0804x over previous
#include <cuda_runtime.h>
#include <cuda_fp16.h>

// Problem geometry
#define S      160
#define NB     4
#define SLICE  (S * S)              // 25600
#define S3     (S * S * S)          // 4,096,000
#define NVOX   (NB * S3)            // 16,384,000
#define SSIM_C1 0.0001f
#define SSIM_C2 0.0009f

// H-tiling (TH multiple of 11 -> window shifts rename away)
#define TH     22                   // outputs per block along h
#define HROWS  (TH + 10)            // 32 input rows incl. halo
#define NTILE  8                    // 8*22 = 176 >= 160 (guarded)
#define PW     172                  // padded row width

// K3 segmentation
#define DSEG   2
#define DLEN   (S / DSEG)           // 80
#define NPART  (S * NB * DSEG)      // 1280 partials

// Scratch after W+H conv. One uint2 per voxel:
//   .x = half2(mu1pre, mu2pre), .y = half2(xx+yy, xy).
// Layout [n][h][d][w]  ->  K3's D-conv steps are 1280B-stride (L2-local).
__device__ uint2 g_buf[NVOX];
__device__ float g_part[NPART];

// 11-tap Gaussian, sigma=1.5 (symmetric: 6 distinct values).
#define GW_INIT { 0.00102838f, 0.00759875f, 0.03600078f, 0.10936070f, \
                  0.21300554f, 0.26601172f, 0.21300554f, 0.10936070f, \
                  0.03600078f, 0.00759875f, 0.00102838f }

// ---------------------------------------------------------------------------
// Packed f32x2 helpers (Blackwell; ptxas never auto-fuses these)
// ---------------------------------------------------------------------------
typedef unsigned long long ull;

__device__ __forceinline__ ull pk2(float lo, float hi) {
    ull r; asm("mov.b64 %0, {%1, %2};" : "=l"(r) : "f"(lo), "f"(hi)); return r;
}
__device__ __forceinline__ void upk2(ull v, float& lo, float& hi) {
    asm("mov.b64 {%0, %1}, %2;" : "=f"(lo), "=f"(hi) : "l"(v));
}
__device__ __forceinline__ ull fma2(ull a, ull b, ull c) {
    ull d; asm("fma.rn.f32x2 %0, %1, %2, %3;" : "=l"(d) : "l"(a), "l"(b), "l"(c));
    return d;
}

#define G2(k) g2v[(k) < 6 ? (k) : 10 - (k)]

__device__ __forceinline__ unsigned h2u(__half2 h) {
    return *reinterpret_cast<unsigned*>(&h);
}
__device__ __forceinline__ __half2 u2h(unsigned u) {
    return *reinterpret_cast<__half2*>(&u);
}

// ---------------------------------------------------------------------------
// K12: fused products + W-conv + H-conv, thread-per-column.
// Per tap: fma2 on (a,b); scalar a^2+b^2 and a*b packed once; fma2 on (P,Q).
// No cross-pair unpack in the tap loop.
// ---------------------------------------------------------------------------
extern __shared__ float2 s_xy[];     // [HROWS][PW]

__device__ __forceinline__ void wconv_pk(
    const float2* __restrict__ r, const ull* g2v, ull& ab, ull& pq)
{
    ab = 0ull; pq = 0ull;
    #pragma unroll
    for (int k = 0; k < 11; ++k) {
        const float2 v = r[k];
        ab = fma2(G2(k), pk2(v.x, v.y), ab);              // (Sg*a, Sg*b)
        const float s = fmaf(v.x, v.x, v.y * v.y);        // a^2 + b^2
        const float q = v.x * v.y;                        // a*b
        pq = fma2(G2(k), pk2(s, q), pq);                  // (Sg*s, Sg*q)
    }
}

__global__ __launch_bounds__(160, 5) void k12_wh(
    const float* __restrict__ x, const float* __restrict__ y)
{
    const float GW[11] = GW_INIT;
    ull g2v[6];
    #pragma unroll
    for (int k = 0; k < 6; ++k) g2v[k] = pk2(GW[k], GW[k]);

    const int ht = blockIdx.x;
    const int d  = blockIdx.y;
    const int n  = blockIdx.z;
    const int h0 = ht * TH;
    const int tid = threadIdx.x;
    const size_t ibase = (size_t)n * S3 + (size_t)d * SLICE;   // input slice

    // Load HROWS padded input rows (zeros at h and w edges), coalesced.
    for (int i = tid; i < HROWS * PW; i += 160) {
        const int r = i / PW, p = i - r * PW;
        const int hh = h0 - 5 + r;
        const int ww = p - 6;          // col p holds w = p-6
        float a = 0.f, b = 0.f;
        if (hh >= 0 && hh < S && ww >= 0 && ww < S) {
            const size_t g = ibase + (size_t)hh * S + ww;
            a = x[g]; b = y[g];
        }
        s_xy[i] = make_float2(a, b);
    }
    __syncthreads();

    const int w = tid;
    const int cbase = w + 1;           // padded col of tap k: w+1+k

    ull wab[11], wpq[11];
    #pragma unroll
    for (int k = 0; k < 11; ++k)
        wconv_pk(s_xy + k * PW + cbase, g2v, wab[k], wpq[k]);

    // output base for layout [n][h][d][w]
    const size_t obase = (size_t)n * S3 + (size_t)d * S + w;

    for (int ob = 0; ob < TH; ob += 11) {
        #pragma unroll
        for (int u = 0; u < 11; ++u) {
            const int o = ob + u;
            const int h = h0 + o;
            if (h < S) {
                ull accAB = 0ull, accPQ = 0ull;
                #pragma unroll
                for (int k = 0; k < 11; ++k) {
                    accAB = fma2(G2(k), wab[k], accAB);
                    accPQ = fma2(G2(k), wpq[k], accPQ);
                }
                float A, B, P, Q;
                upk2(accAB, A, B);
                upk2(accPQ, P, Q);
                uint2 st;
                st.x = h2u(__floats2half2_rn(A, B));
                st.y = h2u(__floats2half2_rn(P, Q));
                g_buf[obase + (size_t)h * SLICE] = st;
            }
            #pragma unroll
            for (int k = 0; k < 10; ++k) {
                wab[k] = wab[k+1]; wpq[k] = wpq[k+1];
            }
            if (o + 11 < HROWS)
                wconv_pk(s_xy + (o + 11) * PW + cbase, g2v, wab[10], wpq[10]);
        }
    }
}

// ---------------------------------------------------------------------------
// K3: conv along D (2 segments of 80) + fused SSIM + block partials.
// Batched 11-deep prefetch per unrolled group -> MLP=11 hides DRAM latency.
// ---------------------------------------------------------------------------
__global__ __launch_bounds__(S) void k3_dconv_ssim()
{
    const float GW[11] = GW_INIT;
    const int h   = blockIdx.x;
    const int n   = blockIdx.y;
    const int seg = blockIdx.z;
    const int d0  = seg * DLEN;
    const int w   = threadIdx.x;

    const uint2* __restrict__ src =
        g_buf + (size_t)n * S3 + (size_t)h * SLICE + w;

    float w0[11], w1[11], w2[11], w3[11];
    #pragma unroll
    for (int k = 0; k < 11; ++k) {
        const int dd = d0 - 5 + k;
        if (dd >= 0 && dd < S) {
            const uint2 v = src[(size_t)dd * S];
            const float2 vp = __half22float2(u2h(v.x));
            const float2 vq = __half22float2(u2h(v.y));
            w0[k] = vp.x; w1[k] = vp.y; w2[k] = vq.x; w3[k] = vq.y;
        } else {
            w0[k] = 0.f; w1[k] = 0.f; w2[k] = 0.f; w3[k] = 0.f;
        }
    }

    float lsum = 0.f;

    for (int ob = 0; ob < 88; ob += 11) {
        // ---- batch prefetch: values pushed by steps u=0..10 of this group
        uint2 nxt[11];
        #pragma unroll
        for (int u = 0; u < 11; ++u) {
            const int o  = ob + u;
            const int dd = d0 + o + 6;
            if (o < DLEN - 1 && dd < S)
                nxt[u] = src[(size_t)dd * S];
            else
                nxt[u] = make_uint2(0u, 0u);   // half2 zero bits = +0.0
        }
        // ---- compute 11 outputs
        #pragma unroll
        for (int u = 0; u < 11; ++u) {
            const int o = ob + u;
            if (o < DLEN) {
                float mu1 = 0.f, mu2 = 0.f, pp = 0.f, qq = 0.f;
                #pragma unroll
                for (int k = 0; k < 11; ++k) {
                    const float g = GW[k];
                    mu1 += g * w0[k]; mu2 += g * w1[k];
                    pp  += g * w2[k]; qq  += g * w3[k];
                }
                const float mu1sq = mu1 * mu1;
                const float mu2sq = mu2 * mu2;
                const float mu12  = mu1 * mu2;
                const float s1s2  = pp - mu1sq - mu2sq;
                const float s12   = qq - mu12;
                const float num = (2.f * mu12 + SSIM_C1) * (2.f * s12 + SSIM_C2);
                const float den = (mu1sq + mu2sq + SSIM_C1) * (s1s2 + SSIM_C2);
                lsum += __fdividef(num, den);
            }
            #pragma unroll
            for (int k = 0; k < 10; ++k) {
                w0[k] = w0[k+1]; w1[k] = w1[k+1];
                w2[k] = w2[k+1]; w3[k] = w3[k+1];
            }
            const float2 vp = __half22float2(u2h(nxt[u].x));
            const float2 vq = __half22float2(u2h(nxt[u].y));
            w0[10] = vp.x; w1[10] = vp.y; w2[10] = vq.x; w3[10] = vq.y;
        }
    }

    #pragma unroll
    for (int t = 16; t > 0; t >>= 1)
        lsum += __shfl_xor_sync(0xffffffffu, lsum, t);
    __shared__ float red[5];
    const int wid = w >> 5, lane = w & 31;
    if (lane == 0) red[wid] = lsum;
    __syncthreads();
    if (w == 0) {
        const int b = blockIdx.x + S * (blockIdx.y + NB * blockIdx.z);
        g_part[b] = red[0] + red[1] + red[2] + red[3] + red[4];
    }
}

// ---------------------------------------------------------------------------
// K4: reduce 1280 partials -> scalar loss
// ---------------------------------------------------------------------------
__global__ __launch_bounds__(256) void k4_finalize(float* __restrict__ out)
{
    const int tid = threadIdx.x;
    float s = 0.f;
    for (int i = tid; i < NPART; i += 256) s += g_part[i];
    #pragma unroll
    for (int t = 16; t > 0; t >>= 1)
        s += __shfl_xor_sync(0xffffffffu, s, t);
    __shared__ float red[8];
    if ((tid & 31) == 0) red[tid >> 5] = s;
    __syncthreads();
    if (tid == 0) {
        float tot = 0.f;
        #pragma unroll
        for (int i = 0; i < 8; ++i) tot += red[i];
        out[0] = (float)(1.0 - (double)tot / (double)NVOX);
    }
}

// ---------------------------------------------------------------------------
extern "C" void kernel_launch(void* const* d_in, const int* in_sizes, int n_in,
                              void* d_out, int out_size)
{
    const float* img1 = (const float*)d_in[0];
    const float* img2 = (const float*)d_in[1];
    float* out = (float*)d_out;

    const int k12_smem = HROWS * PW * (int)sizeof(float2);   // 44032 B
    cudaFuncSetAttribute(k12_wh, cudaFuncAttributeMaxDynamicSharedMemorySize,
                         k12_smem);

    k12_wh<<<dim3(NTILE, S, NB), 160, k12_smem>>>(img1, img2);
    k3_dconv_ssim<<<dim3(S, NB, DSEG), S>>>();
    k4_finalize<<<1, 256>>>(out);
}

// round 12
// speedup vs baseline: 1.3646x; 1.0078x over previous
#include <cuda_runtime.h>
#include <cuda_fp16.h>

// Problem geometry
#define S      160
#define NB     4
#define SLICE  (S * S)              // 25600
#define S3     (S * S * S)          // 4,096,000
#define NVOX   (NB * S3)            // 16,384,000
#define SSIM_C1 0.0001f
#define SSIM_C2 0.0009f

// H-tiling: 8 * 20 = 160 exactly -> no guards, no wasted tiles.
#define TH     20                   // outputs per block along h
#define HROWS  (TH + 10)            // 30 input rows incl. halo
#define NTILE  8
#define PW     172                  // padded row width

// K3 segmentation
#define DSEG   2
#define DLEN   (S / DSEG)           // 80
#define NPART  (S * NB * DSEG)      // 1280 partials

// Scratch after W+H conv. One uint2 per voxel:
//   .x = half2(mu1pre, mu2pre), .y = half2(xx+yy, xy).
// Layout [n][h][d][w]  ->  K3's D-conv steps are 1280B-stride (L2-local).
__device__ uint2 g_buf[NVOX];
__device__ float g_part[NPART];

// 11-tap Gaussian, sigma=1.5 (symmetric: 6 distinct values).
#define GW_INIT { 0.00102838f, 0.00759875f, 0.03600078f, 0.10936070f, \
                  0.21300554f, 0.26601172f, 0.21300554f, 0.10936070f, \
                  0.03600078f, 0.00759875f, 0.00102838f }

// ---------------------------------------------------------------------------
// Packed f32x2 helpers (Blackwell; ptxas never auto-fuses these)
// ---------------------------------------------------------------------------
typedef unsigned long long ull;

__device__ __forceinline__ ull pk2(float lo, float hi) {
    ull r; asm("mov.b64 %0, {%1, %2};" : "=l"(r) : "f"(lo), "f"(hi)); return r;
}
__device__ __forceinline__ void upk2(ull v, float& lo, float& hi) {
    asm("mov.b64 {%0, %1}, %2;" : "=f"(lo), "=f"(hi) : "l"(v));
}
__device__ __forceinline__ ull fma2(ull a, ull b, ull c) {
    ull d; asm("fma.rn.f32x2 %0, %1, %2, %3;" : "=l"(d) : "l"(a), "l"(b), "l"(c));
    return d;
}

#define G2(k) g2v[(k) < 6 ? (k) : 10 - (k)]

__device__ __forceinline__ unsigned h2u(__half2 h) {
    return *reinterpret_cast<unsigned*>(&h);
}
__device__ __forceinline__ __half2 u2h(unsigned u) {
    return *reinterpret_cast<__half2*>(&u);
}

// ---------------------------------------------------------------------------
// K12: fused products + W-conv + H-conv, thread-per-column, fully unrolled.
// ---------------------------------------------------------------------------
extern __shared__ float2 s_xy[];     // [HROWS][PW]

__device__ __forceinline__ void wconv_pk(
    const float2* __restrict__ r, const ull* g2v, ull& ab, ull& pq)
{
    ab = 0ull; pq = 0ull;
    #pragma unroll
    for (int k = 0; k < 11; ++k) {
        const float2 v = r[k];
        ab = fma2(G2(k), pk2(v.x, v.y), ab);              // (Sg*a, Sg*b)
        const float s = fmaf(v.x, v.x, v.y * v.y);        // a^2 + b^2
        const float q = v.x * v.y;                        // a*b
        pq = fma2(G2(k), pk2(s, q), pq);                  // (Sg*s, Sg*q)
    }
}

__global__ __launch_bounds__(160, 5) void k12_wh(
    const float* __restrict__ x, const float* __restrict__ y)
{
    const float GW[11] = GW_INIT;
    ull g2v[6];
    #pragma unroll
    for (int k = 0; k < 6; ++k) g2v[k] = pk2(GW[k], GW[k]);

    const int ht = blockIdx.x;
    const int d  = blockIdx.y;
    const int n  = blockIdx.z;
    const int h0 = ht * TH;
    const int tid = threadIdx.x;
    const size_t ibase = (size_t)n * S3 + (size_t)d * SLICE;   // input slice

    // Load HROWS padded input rows (zeros at h and w edges), coalesced.
    for (int i = tid; i < HROWS * PW; i += 160) {
        const int r = i / PW, p = i - r * PW;
        const int hh = h0 - 5 + r;
        const int ww = p - 6;          // col p holds w = p-6
        float a = 0.f, b = 0.f;
        if (hh >= 0 && hh < S && ww >= 0 && ww < S) {
            const size_t g = ibase + (size_t)hh * S + ww;
            a = x[g]; b = y[g];
        }
        s_xy[i] = make_float2(a, b);
    }
    __syncthreads();

    const int w = tid;
    const float2* __restrict__ col = s_xy + w + 1;  // tap k of row r: col[r*PW + k]

    ull wab[11], wpq[11];
    #pragma unroll
    for (int k = 0; k < 11; ++k)
        wconv_pk(col + k * PW, g2v, wab[k], wpq[k]);

    // output base for layout [n][h][d][w]
    uint2* __restrict__ dst =
        g_buf + (size_t)n * S3 + (size_t)(h0) * SLICE + (size_t)d * S + w;

    #pragma unroll
    for (int o = 0; o < TH; ++o) {
        ull accAB = 0ull, accPQ = 0ull;
        #pragma unroll
        for (int k = 0; k < 11; ++k) {
            accAB = fma2(G2(k), wab[k], accAB);
            accPQ = fma2(G2(k), wpq[k], accPQ);
        }
        float A, B, P, Q;
        upk2(accAB, A, B);
        upk2(accPQ, P, Q);
        uint2 st;
        st.x = h2u(__floats2half2_rn(A, B));
        st.y = h2u(__floats2half2_rn(P, Q));
        dst[(size_t)o * SLICE] = st;

        #pragma unroll
        for (int k = 0; k < 10; ++k) {
            wab[k] = wab[k+1]; wpq[k] = wpq[k+1];
        }
        if (o + 11 < HROWS)                         // compile-time under unroll
            wconv_pk(col + (o + 11) * PW, g2v, wab[10], wpq[10]);
    }
}

// ---------------------------------------------------------------------------
// K3: conv along D (2 segments of 80) + fused SSIM + block partials.
// Batched 11-deep prefetch per unrolled group -> MLP=11 hides DRAM latency.
// ---------------------------------------------------------------------------
__global__ __launch_bounds__(S) void k3_dconv_ssim()
{
    const float GW[11] = GW_INIT;
    const int h   = blockIdx.x;
    const int n   = blockIdx.y;
    const int seg = blockIdx.z;
    const int d0  = seg * DLEN;
    const int w   = threadIdx.x;

    const uint2* __restrict__ src =
        g_buf + (size_t)n * S3 + (size_t)h * SLICE + w;

    float w0[11], w1[11], w2[11], w3[11];
    #pragma unroll
    for (int k = 0; k < 11; ++k) {
        const int dd = d0 - 5 + k;
        if (dd >= 0 && dd < S) {
            const uint2 v = src[(size_t)dd * S];
            const float2 vp = __half22float2(u2h(v.x));
            const float2 vq = __half22float2(u2h(v.y));
            w0[k] = vp.x; w1[k] = vp.y; w2[k] = vq.x; w3[k] = vq.y;
        } else {
            w0[k] = 0.f; w1[k] = 0.f; w2[k] = 0.f; w3[k] = 0.f;
        }
    }

    float lsum = 0.f;

    for (int ob = 0; ob < 88; ob += 11) {
        // ---- batch prefetch: values pushed by steps u=0..10 of this group
        uint2 nxt[11];
        #pragma unroll
        for (int u = 0; u < 11; ++u) {
            const int o  = ob + u;
            const int dd = d0 + o + 6;
            if (o < DLEN - 1 && dd < S)
                nxt[u] = src[(size_t)dd * S];
            else
                nxt[u] = make_uint2(0u, 0u);   // half2 zero bits = +0.0
        }
        // ---- compute 11 outputs
        #pragma unroll
        for (int u = 0; u < 11; ++u) {
            const int o = ob + u;
            if (o < DLEN) {
                float mu1 = 0.f, mu2 = 0.f, pp = 0.f, qq = 0.f;
                #pragma unroll
                for (int k = 0; k < 11; ++k) {
                    const float g = GW[k];
                    mu1 += g * w0[k]; mu2 += g * w1[k];
                    pp  += g * w2[k]; qq  += g * w3[k];
                }
                const float mu1sq = mu1 * mu1;
                const float mu2sq = mu2 * mu2;
                const float mu12  = mu1 * mu2;
                const float s1s2  = pp - mu1sq - mu2sq;
                const float s12   = qq - mu12;
                const float num = (2.f * mu12 + SSIM_C1) * (2.f * s12 + SSIM_C2);
                const float den = (mu1sq + mu2sq + SSIM_C1) * (s1s2 + SSIM_C2);
                lsum += __fdividef(num, den);
            }
            #pragma unroll
            for (int k = 0; k < 10; ++k) {
                w0[k] = w0[k+1]; w1[k] = w1[k+1];
                w2[k] = w2[k+1]; w3[k] = w3[k+1];
            }
            const float2 vp = __half22float2(u2h(nxt[u].x));
            const float2 vq = __half22float2(u2h(nxt[u].y));
            w0[10] = vp.x; w1[10] = vp.y; w2[10] = vq.x; w3[10] = vq.y;
        }
    }

    #pragma unroll
    for (int t = 16; t > 0; t >>= 1)
        lsum += __shfl_xor_sync(0xffffffffu, lsum, t);
    __shared__ float red[5];
    const int wid = w >> 5, lane = w & 31;
    if (lane == 0) red[wid] = lsum;
    __syncthreads();
    if (w == 0) {
        const int b = blockIdx.x + S * (blockIdx.y + NB * blockIdx.z);
        g_part[b] = red[0] + red[1] + red[2] + red[3] + red[4];
    }
}

// ---------------------------------------------------------------------------
// K4: reduce 1280 partials -> scalar loss
// ---------------------------------------------------------------------------
__global__ __launch_bounds__(256) void k4_finalize(float* __restrict__ out)
{
    const int tid = threadIdx.x;
    float s = 0.f;
    for (int i = tid; i < NPART; i += 256) s += g_part[i];
    #pragma unroll
    for (int t = 16; t > 0; t >>= 1)
        s += __shfl_xor_sync(0xffffffffu, s, t);
    __shared__ float red[8];
    if ((tid & 31) == 0) red[tid >> 5] = s;
    __syncthreads();
    if (tid == 0) {
        float tot = 0.f;
        #pragma unroll
        for (int i = 0; i < 8; ++i) tot += red[i];
        out[0] = (float)(1.0 - (double)tot / (double)NVOX);
    }
}

// ---------------------------------------------------------------------------
extern "C" void kernel_launch(void* const* d_in, const int* in_sizes, int n_in,
                              void* d_out, int out_size)
{
    const float* img1 = (const float*)d_in[0];
    const float* img2 = (const float*)d_in[1];
    float* out = (float*)d_out;

    const int k12_smem = HROWS * PW * (int)sizeof(float2);   // 41280 B
    cudaFuncSetAttribute(k12_wh, cudaFuncAttributeMaxDynamicSharedMemorySize,
                         k12_smem);

    k12_wh<<<dim3(NTILE, S, NB), 160, k12_smem>>>(img1, img2);
    k3_dconv_ssim<<<dim3(S, NB, DSEG), S>>>();
    k4_finalize<<<1, 256>>>(out);
}

// round 14
// speedup vs baseline: 1.3676x; 1.0022x over previous
#include <cuda_runtime.h>
#include <cuda_fp16.h>

// Problem geometry
#define S      160
#define NB     4
#define SLICE  (S * S)              // 25600
#define S3     (S * S * S)          // 4,096,000
#define NVOX   (NB * S3)            // 16,384,000
#define SSIM_C1 0.0001f
#define SSIM_C2 0.0009f

// H-tiling: 8 * 20 = 160 exactly -> no guards, no wasted tiles.
#define TH     20                   // outputs per block along h
#define HROWS  (TH + 10)            // 30 input rows incl. halo
#define NTILE  8
#define PW     172                  // padded row width

// K3 segmentation
#define DSEG   2
#define DLEN   (S / DSEG)           // 80
#define NPART  (S * NB * DSEG)      // 1280 partials

// Scratch after W+H conv. One uint2 per voxel:
//   .x = half2(mu1pre, mu2pre), .y = half2(xx+yy, xy).
// fp16 is STORAGE ONLY -- all accumulation is fp32 (R13 lesson).
// Layout [n][h][d][w] -> K3's D-conv steps are 1280B-stride (L2-local).
__device__ uint2 g_buf[NVOX];
__device__ float g_part[NPART];

// 11-tap Gaussian, sigma=1.5 (symmetric: 6 distinct values).
#define GW_INIT { 0.00102838f, 0.00759875f, 0.03600078f, 0.10936070f, \
                  0.21300554f, 0.26601172f, 0.21300554f, 0.10936070f, \
                  0.03600078f, 0.00759875f, 0.00102838f }

// ---------------------------------------------------------------------------
// Packed f32x2 helpers (Blackwell; ptxas never auto-fuses these)
// ---------------------------------------------------------------------------
typedef unsigned long long ull;

__device__ __forceinline__ ull pk2(float lo, float hi) {
    ull r; asm("mov.b64 %0, {%1, %2};" : "=l"(r) : "f"(lo), "f"(hi)); return r;
}
__device__ __forceinline__ void upk2(ull v, float& lo, float& hi) {
    asm("mov.b64 {%0, %1}, %2;" : "=f"(lo), "=f"(hi) : "l"(v));
}
__device__ __forceinline__ ull fma2(ull a, ull b, ull c) {
    ull d; asm("fma.rn.f32x2 %0, %1, %2, %3;" : "=l"(d) : "l"(a), "l"(b), "l"(c));
    return d;
}

#define G2(k) g2v[(k) < 6 ? (k) : 10 - (k)]

__device__ __forceinline__ unsigned h2u(__half2 h) {
    return *reinterpret_cast<unsigned*>(&h);
}
__device__ __forceinline__ __half2 u2h(unsigned u) {
    return *reinterpret_cast<__half2*>(&u);
}

// ---------------------------------------------------------------------------
// K12: fused products + W-conv + H-conv, thread-per-column, fully unrolled.
// fp32 accumulation throughout (R12-exact). fp16 only at the final store.
// ---------------------------------------------------------------------------
extern __shared__ float2 s_xy[];     // [HROWS][PW]

__device__ __forceinline__ void wconv_pk(
    const float2* __restrict__ r, const ull* g2v, ull& ab, ull& pq)
{
    ab = 0ull; pq = 0ull;
    #pragma unroll
    for (int k = 0; k < 11; ++k) {
        const float2 v = r[k];
        ab = fma2(G2(k), pk2(v.x, v.y), ab);              // (Sg*a, Sg*b)
        const float s = fmaf(v.x, v.x, v.y * v.y);        // a^2 + b^2
        const float q = v.x * v.y;                        // a*b
        pq = fma2(G2(k), pk2(s, q), pq);                  // (Sg*s, Sg*q)
    }
}

__global__ __launch_bounds__(160, 5) void k12_wh(
    const float* __restrict__ x, const float* __restrict__ y)
{
    const float GW[11] = GW_INIT;
    ull g2v[6];
    #pragma unroll
    for (int k = 0; k < 6; ++k) g2v[k] = pk2(GW[k], GW[k]);

    const int ht = blockIdx.x;
    const int d  = blockIdx.y;
    const int n  = blockIdx.z;
    const int h0 = ht * TH;
    const int tid = threadIdx.x;
    const size_t ibase = (size_t)n * S3 + (size_t)d * SLICE;   // input slice

    // Load HROWS padded input rows (zeros at h and w edges), coalesced.
    for (int i = tid; i < HROWS * PW; i += 160) {
        const int r = i / PW, p = i - r * PW;
        const int hh = h0 - 5 + r;
        const int ww = p - 6;          // col p holds w = p-6
        float a = 0.f, b = 0.f;
        if (hh >= 0 && hh < S && ww >= 0 && ww < S) {
            const size_t g = ibase + (size_t)hh * S + ww;
            a = x[g]; b = y[g];
        }
        s_xy[i] = make_float2(a, b);
    }
    __syncthreads();

    const int w = tid;
    const float2* __restrict__ col = s_xy + w + 1;  // tap k of row r: col[r*PW + k]

    ull wab[11], wpq[11];
    #pragma unroll
    for (int k = 0; k < 11; ++k)
        wconv_pk(col + k * PW, g2v, wab[k], wpq[k]);

    // output base for layout [n][h][d][w]
    uint2* __restrict__ dst =
        g_buf + (size_t)n * S3 + (size_t)h0 * SLICE + (size_t)d * S + w;

    #pragma unroll
    for (int o = 0; o < TH; ++o) {
        ull accAB = 0ull, accPQ = 0ull;
        #pragma unroll
        for (int k = 0; k < 11; ++k) {
            accAB = fma2(G2(k), wab[k], accAB);
            accPQ = fma2(G2(k), wpq[k], accPQ);
        }
        float A, B, P, Q;
        upk2(accAB, A, B);
        upk2(accPQ, P, Q);
        uint2 st;
        st.x = h2u(__floats2half2_rn(A, B));
        st.y = h2u(__floats2half2_rn(P, Q));
        dst[(size_t)o * SLICE] = st;

        #pragma unroll
        for (int k = 0; k < 10; ++k) {
            wab[k] = wab[k+1]; wpq[k] = wpq[k+1];
        }
        if (o + 11 < HROWS)                         // compile-time under unroll
            wconv_pk(col + (o + 11) * PW, g2v, wab[10], wpq[10]);
    }
}

// ---------------------------------------------------------------------------
// K3: conv along D (2 segments of 80) + fused SSIM + block partials.
// Packed f32x2 windows (pk2 of cvt results = register-pair rename):
// 22 fma2 per output instead of 44 FFMA; bitwise-identical rounding.
// Batched 11-deep prefetch -> MLP=11 hides DRAM latency.
// ---------------------------------------------------------------------------
__global__ __launch_bounds__(S) void k3_dconv_ssim()
{
    const float GW[11] = GW_INIT;
    ull g2v[6];
    #pragma unroll
    for (int k = 0; k < 6; ++k) g2v[k] = pk2(GW[k], GW[k]);

    const int h   = blockIdx.x;
    const int n   = blockIdx.y;
    const int seg = blockIdx.z;
    const int d0  = seg * DLEN;
    const int w   = threadIdx.x;

    const uint2* __restrict__ src =
        g_buf + (size_t)n * S3 + (size_t)h * SLICE + w;

    ull wab[11], wsq[11];
    #pragma unroll
    for (int k = 0; k < 11; ++k) {
        const int dd = d0 - 5 + k;
        if (dd >= 0 && dd < S) {
            const uint2 v = src[(size_t)dd * S];
            const float2 vp = __half22float2(u2h(v.x));
            const float2 vq = __half22float2(u2h(v.y));
            wab[k] = pk2(vp.x, vp.y);
            wsq[k] = pk2(vq.x, vq.y);
        } else {
            wab[k] = 0ull; wsq[k] = 0ull;
        }
    }

    float lsum = 0.f;

    for (int ob = 0; ob < 88; ob += 11) {
        // ---- batch prefetch: values pushed by steps u=0..10 of this group
        uint2 nxt[11];
        #pragma unroll
        for (int u = 0; u < 11; ++u) {
            const int o  = ob + u;
            const int dd = d0 + o + 6;
            if (o < DLEN - 1 && dd < S)
                nxt[u] = src[(size_t)dd * S];
            else
                nxt[u] = make_uint2(0u, 0u);
        }
        // ---- compute 11 outputs
        #pragma unroll
        for (int u = 0; u < 11; ++u) {
            const int o = ob + u;
            if (o < DLEN) {
                ull accAB = 0ull, accSQ = 0ull;
                #pragma unroll
                for (int k = 0; k < 11; ++k) {
                    accAB = fma2(G2(k), wab[k], accAB);
                    accSQ = fma2(G2(k), wsq[k], accSQ);
                }
                float mu1, mu2, pp, qq;
                upk2(accAB, mu1, mu2);
                upk2(accSQ, pp, qq);
                const float mu1sq = mu1 * mu1;
                const float mu2sq = mu2 * mu2;
                const float mu12  = mu1 * mu2;
                const float s1s2  = pp - mu1sq - mu2sq;
                const float s12   = qq - mu12;
                const float num = (2.f * mu12 + SSIM_C1) * (2.f * s12 + SSIM_C2);
                const float den = (mu1sq + mu2sq + SSIM_C1) * (s1s2 + SSIM_C2);
                lsum += __fdividef(num, den);
            }
            #pragma unroll
            for (int k = 0; k < 10; ++k) {
                wab[k] = wab[k+1]; wsq[k] = wsq[k+1];
            }
            const float2 vp = __half22float2(u2h(nxt[u].x));
            const float2 vq = __half22float2(u2h(nxt[u].y));
            wab[10] = pk2(vp.x, vp.y);
            wsq[10] = pk2(vq.x, vq.y);
        }
    }

    #pragma unroll
    for (int t = 16; t > 0; t >>= 1)
        lsum += __shfl_xor_sync(0xffffffffu, lsum, t);
    __shared__ float red[5];
    const int wid = w >> 5, lane = w & 31;
    if (lane == 0) red[wid] = lsum;
    __syncthreads();
    if (w == 0) {
        const int b = blockIdx.x + S * (blockIdx.y + NB * blockIdx.z);
        g_part[b] = red[0] + red[1] + red[2] + red[3] + red[4];
    }
}

// ---------------------------------------------------------------------------
// K4: reduce 1280 partials -> scalar loss
// ---------------------------------------------------------------------------
__global__ __launch_bounds__(256) void k4_finalize(float* __restrict__ out)
{
    const int tid = threadIdx.x;
    float s = 0.f;
    for (int i = tid; i < NPART; i += 256) s += g_part[i];
    #pragma unroll
    for (int t = 16; t > 0; t >>= 1)
        s += __shfl_xor_sync(0xffffffffu, s, t);
    __shared__ float red[8];
    if ((tid & 31) == 0) red[tid >> 5] = s;
    __syncthreads();
    if (tid == 0) {
        float tot = 0.f;
        #pragma unroll
        for (int i = 0; i < 8; ++i) tot += red[i];
        out[0] = (float)(1.0 - (double)tot / (double)NVOX);
    }
}

// ---------------------------------------------------------------------------
extern "C" void kernel_launch(void* const* d_in, const int* in_sizes, int n_in,
                              void* d_out, int out_size)
{
    const float* img1 = (const float*)d_in[0];
    const float* img2 = (const float*)d_in[1];
    float* out = (float*)d_out;

    const int k12_smem = HROWS * PW * (int)sizeof(float2);   // 41280 B
    cudaFuncSetAttribute(k12_wh, cudaFuncAttributeMaxDynamicSharedMemorySize,
                         k12_smem);

    k12_wh<<<dim3(NTILE, S, NB), 160, k12_smem>>>(img1, img2);
    k3_dconv_ssim<<<dim3(S, NB, DSEG), S>>>();
    k4_finalize<<<1, 256>>>(out);
}